// round 10
// baseline (speedup 1.0000x reference)
#include <cuda_runtime.h>
#include <cuda_fp16.h>
#include <cstdint>

#define HID   128
#define NB    16
#define NPTS  10000
#define OUTD  5
#define LTOT  160000
#define BP    128

// ---------------- device scratch (no allocation allowed) -------------------
__device__ float g_gate[4 * NB * HID];
__device__ float g_M[NB * HID * 8];      // gate3-folded Wtf@bc^T, padded 8
__device__ float g_c[NB * 8];
// Pre-transposed fp16-split pre-swizzled weights:
// [l][half][plane: wh/wl][n=128][k=64] fp16  (layer l = 32768 halves contiguous)
__device__ __align__(16) __half g_WT[6 * 16384];

// SMEM byte map (per CTA, dynamic):
//  [0,32768)       X plane [128 p][128 k] fp16, row 256B, swz ((p&7)<<4)
//  [32768,98304)   W stage FULL layer: [half][plane][128 n][64 k] fp16
//  [98304,106496)  params (2048 floats)
//  [106496,111616) final-contraction partials (1280 floats)
#define SM_X    0
#define SM_W    32768
#define SM_PAR  98304
#define SM_PART 106496
#define SM_TOTAL 111616
#define PAR_BT0 0
#define PAR_W0  128
#define PAR_AT  640
#define PAR_WT  1152
#define PAR_BT  1664

__device__ __forceinline__ float rowdy_f(float t, float a, float w) {
    float th; asm("tanh.approx.f32 %0, %1;" : "=f"(th) : "f"(t));
    return th + a * __sinf(w * t);
}
__device__ __forceinline__ void cp_async16(uint32_t smem_dst, const void* gmem_src) {
    asm volatile("cp.async.cg.shared.global [%0], [%1], 16;" :: "r"(smem_dst), "l"(gmem_src));
}
__device__ __forceinline__ void ldsm4(uint32_t* r, uint32_t a) {
    asm volatile("ldmatrix.sync.aligned.m8n8.x4.shared.b16 {%0,%1,%2,%3}, [%4];"
                 : "=r"(r[0]), "=r"(r[1]), "=r"(r[2]), "=r"(r[3]) : "r"(a));
}
__device__ __forceinline__ void mma16816(float* d, const uint32_t* a,
                                         uint32_t b0, uint32_t b1) {
    asm volatile(
        "mma.sync.aligned.m16n8k16.row.col.f32.f16.f16.f32 "
        "{%0,%1,%2,%3}, {%4,%5,%6,%7}, {%8,%9}, {%0,%1,%2,%3};"
        : "+f"(d[0]), "+f"(d[1]), "+f"(d[2]), "+f"(d[3])
        : "r"(a[0]), "r"(a[1]), "r"(a[2]), "r"(a[3]), "r"(b0), "r"(b1));
}
// pack (x0,x1) to fp16x2 and store to X plane
__device__ __forceinline__ void store_x(uint32_t su, int p, int j,
                                        float x0, float x1) {
    uint32_t hx;
    asm("cvt.rn.f16x2.f32 %0, %1, %2;" : "=r"(hx) : "f"(x1), "f"(x0));
    uint32_t off = (uint32_t)(p * 256) + (uint32_t)((j * 2) ^ ((p & 7) << 4));
    asm volatile("st.shared.b32 [%0], %1;" :: "r"(su + SM_X + off), "r"(hx));
}
// stage one FULL layer of split weights (64KB) and commit
__device__ __forceinline__ void stage_W(uint32_t su, const __half* src, int tid) {
#pragma unroll
    for (int i = 0; i < 16; i++)
        cp_async16(su + SM_W + (uint32_t)(tid + i * 256) * 16,
                   (const char*)src + (tid + i * 256) * 16);
    asm volatile("cp.async.commit_group;");
}

// ---------------------------------------------------------------------------
// Branch MLP + gates + folded matrices (blocks 0..15) and weight prep
// (blocks 16..111): W^T + fp16 split + SMEM-image swizzle into g_WT.
// ---------------------------------------------------------------------------
__global__ void __launch_bounds__(512, 1) branch_prep_kernel(
    const float* __restrict__ params, const float* __restrict__ Wb0,
    const float* __restrict__ bb0,    const float* __restrict__ Wb,
    const float* __restrict__ bb,     const float* __restrict__ Wbf,
    const float* __restrict__ bbf,    const float* __restrict__ ab,
    const float* __restrict__ wb,     const float* __restrict__ Wtf,
    const float* __restrict__ btf,    const float* __restrict__ Wt)
{
    const int tid = threadIdx.x;

    if (blockIdx.x >= NB) {
        int base = (blockIdx.x - NB) * 512 + tid;
#pragma unroll
        for (int r = 0; r < 2; r++) {
            int idx = base + r * 49152;
            int k     = idx & 63;
            int n     = (idx >> 6) & 127;
            int plane = (idx >> 13) & 1;
            int lh    = idx >> 14;            // l*2 + h
            int l = lh >> 1, h = lh & 1;
            float w = Wt[l * 16384 + (h * 64 + k) * 128 + n];
            __half wh = __float2half_rn(w);
            __half val;
            if (plane == 0) val = wh;
            else            val = __float2half_rn(w - __half2float(wh));
            g_WT[lh * 16384 + plane * 8192 + n * 64 + (k ^ ((n & 7) << 3))] = val;
        }
        return;
    }

    const int b = blockIdx.x;
    const int j = tid & 127;
    const int q = tid >> 7;

    __shared__ float sh_h[HID];
    __shared__ float sh_part[4 * HID];
    __shared__ float sh_bc[OUTD][HID];
    __shared__ float sh_p[8];

    if (tid < 6) sh_p[tid] = params[b * 6 + tid];
    __syncthreads();

    float h = 0.f, gate = 0.f;
    if (q == 0) {
        float t = bb0[j];
#pragma unroll
        for (int k = 0; k < 6; k++) t += sh_p[k] * Wb0[k * HID + j];
        h = tanhf(t) + ab[j] * __sinf(wb[j] * t);
        gate = h;
        sh_h[j] = h;
        g_gate[(0 * NB + b) * HID + j] = gate;
    }
    __syncthreads();

    for (int i = 0; i < 3; i++) {
        const float* W = Wb + i * HID * HID;
        float tp = 0.f;
#pragma unroll 8
        for (int k = q * 32; k < q * 32 + 32; k++) tp += sh_h[k] * W[k * HID + j];
        sh_part[q * HID + j] = tp;
        __syncthreads();
        if (q == 0) {
            float t2 = bb[i * HID + j] + sh_part[j] + sh_part[HID + j]
                     + sh_part[2 * HID + j] + sh_part[3 * HID + j];
            h = tanhf(t2) + ab[(i + 1) * HID + j] * __sinf(wb[(i + 1) * HID + j] * t2);
            sh_h[j] = h;
            gate += h;
            g_gate[((i + 1) * NB + b) * HID + j] = gate;
        }
        __syncthreads();
    }

    {
        float tb[OUTD] = {0.f, 0.f, 0.f, 0.f, 0.f};
#pragma unroll 4
        for (int k = q * 32; k < q * 32 + 32; k++) {
            float hv = sh_h[k];
#pragma unroll
            for (int o = 0; o < OUTD; o++)
                tb[o] += hv * Wbf[k * (HID * OUTD) + o * HID + j];
        }
#pragma unroll
        for (int o = 0; o < OUTD; o++) {
            sh_part[q * HID + j] = tb[o];
            __syncthreads();
            if (q == 0)
                sh_bc[o][j] = bbf[o * HID + j] + sh_part[j] + sh_part[HID + j]
                            + sh_part[2 * HID + j] + sh_part[3 * HID + j];
            __syncthreads();
        }
    }

    {
        float am[OUTD] = {0.f, 0.f, 0.f, 0.f, 0.f};
#pragma unroll 4
        for (int hh = q * 32; hh < q * 32 + 32; hh++) {
            float w = __ldg(&Wtf[j * HID + hh]);
#pragma unroll
            for (int o = 0; o < OUTD; o++) am[o] += w * sh_bc[o][hh];
        }
#pragma unroll
        for (int o = 0; o < OUTD; o++) {
            sh_part[q * HID + j] = am[o];
            __syncthreads();
            if (q == 0)
                g_M[(b * HID + j) * 8 + o] = gate *
                    (sh_part[j] + sh_part[HID + j] + sh_part[2 * HID + j] + sh_part[3 * HID + j]);
            __syncthreads();
        }
        if (q == 0) { g_M[(b * HID + j) * 8 + 5] = 0.f;
                      g_M[(b * HID + j) * 8 + 6] = 0.f;
                      g_M[(b * HID + j) * 8 + 7] = 0.f; }
    }
    if (tid < OUTD) {
        float c = 0.f;
#pragma unroll 8
        for (int hh = 0; hh < HID; hh++) c += btf[hh] * sh_bc[tid][hh];
        g_c[b * 8 + tid] = c;
    }
    if (tid >= OUTD && tid < 8) g_c[b * 8 + tid] = 0.f;
}

// ---------------------------------------------------------------------------
// Trunk: HMMA fp16 2-term W-split, full-layer W staging (one wait per layer,
// no mid-layer drain). 256 threads, 8 warps (4M x 2N), warp tile 32x64.
// ---------------------------------------------------------------------------
__global__ void __launch_bounds__(256, 2)
trunk_kernel(const float* __restrict__ coords, const float* __restrict__ sdf,
             const float* __restrict__ Wt0,    const float* __restrict__ bt0,
             const float* __restrict__ bt,     const float* __restrict__ at,
             const float* __restrict__ wt,     float* __restrict__ out)
{
    extern __shared__ char smem[];
    float* sp  = (float*)(smem + SM_PAR);
    float* scr = (float*)smem;                  // fp32 scratch aliases X + W.half0
    const uint32_t su = (uint32_t)__cvta_generic_to_shared(smem);

    const int tid  = threadIdx.x;
    const int lane = tid & 31;
    const int wid  = tid >> 5;
    const int wm   = wid & 3;
    const int wn   = wid >> 2;
    const int la7  = lane & 7;
    const int lb3  = (lane >> 3) & 1;
    const int lb4  = lane >> 4;
    const int gid  = lane >> 2;
    const int tig  = lane & 3;
    const uint32_t swz = (uint32_t)la7 << 4;

    const int p0     = blockIdx.x * BP;
    const int bstart = p0 / NPTS;
    const int bound  = (bstart + 1) * NPTS - p0;
    const int b1     = (bstart + 1 < NB) ? bstart + 1 : NB - 1;

    // stage full layer-1 W (64KB) immediately; hidden under layer 0 compute
    stage_W(su, g_WT, tid);

    if (tid < 128) sp[PAR_BT0 + tid] = bt0[tid];
    for (int i = tid; i < 512; i += 256) {
        sp[PAR_W0 + i] = Wt0[i];
        sp[PAR_AT + i] = at[i];
        sp[PAR_WT + i] = wt[i];
    }
    for (int i = tid; i < 384; i += 256) sp[PAR_BT + i] = bt[i];
    __syncthreads();

    // ---- layer 0: 2 threads per point, 64 features each ----
    {
        const int p  = tid & 127;
        const int jh = tid >> 7;
        const int gp = p0 + p;
        float c0 = coords[gp * 3 + 0];
        float c1 = coords[gp * 3 + 1];
        float c2 = coords[gp * 3 + 2];
        float c3 = sdf[gp];
        const int bpt = (p < bound) ? bstart : b1;
        const float* gv = &g_gate[(0 * NB + bpt) * HID];
#pragma unroll 4
        for (int i = 0; i < 32; i++) {
            int j = jh * 64 + 2 * i;
            float t0 = sp[PAR_BT0 + j]
                     + c0 * sp[PAR_W0 + j]       + c1 * sp[PAR_W0 + 128 + j]
                     + c2 * sp[PAR_W0 + 256 + j] + c3 * sp[PAR_W0 + 384 + j];
            float t1 = sp[PAR_BT0 + j + 1]
                     + c0 * sp[PAR_W0 + j + 1]       + c1 * sp[PAR_W0 + 128 + j + 1]
                     + c2 * sp[PAR_W0 + 256 + j + 1] + c3 * sp[PAR_W0 + 384 + j + 1];
            float x0 = rowdy_f(t0, sp[PAR_AT + j], sp[PAR_WT + j]) * __ldg(&gv[j]);
            float x1 = rowdy_f(t1, sp[PAR_AT + j + 1], sp[PAR_WT + j + 1]) * __ldg(&gv[j + 1]);
            store_x(su, p, j, x0, x1);
        }
    }

    float acc[2][8][4];

    // ---- layers 1..3 ----
    for (int l = 1; l <= 3; l++) {
        asm volatile("cp.async.wait_group 0;");
        __syncthreads();       // W staged + X writes visible

#pragma unroll
        for (int s = 0; s < 2; s++)
#pragma unroll
            for (int t = 0; t < 8; t++)
#pragma unroll
                for (int i = 0; i < 4; i++) acc[s][t][i] = 0.f;

        // 8 uninterrupted k-steps over the full layer
#pragma unroll
        for (int ks = 0; ks < 8; ks++) {
            const int kl = ks & 3;
            const uint32_t wbase = su + SM_W + (uint32_t)(ks >> 2) * 32768;
            uint32_t a[2][4];
#pragma unroll
            for (int s = 0; s < 2; s++) {
                uint32_t arow = (uint32_t)(wm * 32 + s * 16 + la7 + 8 * lb3);
                uint32_t aoff = ((uint32_t)(ks * 32 + 16 * lb4)) ^ swz;
                ldsm4(a[s], su + SM_X + arow * 256 + aoff);
            }
#pragma unroll
            for (int q = 0; q < 4; q++) {
                uint32_t bh[4], bl[4];
                uint32_t nrow = (uint32_t)(wn * 64 + q * 16 + la7 + 8 * lb4);
                uint32_t boff = ((uint32_t)(kl * 32 + 16 * lb3)) ^ swz;
                ldsm4(bh, wbase + nrow * 128 + boff);
                ldsm4(bl, wbase + 16384 + nrow * 128 + boff);
#pragma unroll
                for (int s = 0; s < 2; s++) {
#pragma unroll
                    for (int u = 0; u < 2; u++) {
                        float* d = acc[s][q * 2 + u];
                        mma16816(d, a[s], bh[2 * u], bh[2 * u + 1]);
                        mma16816(d, a[s], bl[2 * u], bl[2 * u + 1]);
                    }
                }
            }
        }
        __syncthreads();       // all X + W reads of this layer done

        if (l < 3) stage_W(su, g_WT + l * 32768, tid);   // overlaps epilogue

        const float* bvec = &sp[PAR_BT + (l - 1) * 128];
        const float* avec = &sp[PAR_AT + l * 128];
        const float* wvec = &sp[PAR_WT + l * 128];
#pragma unroll
        for (int s = 0; s < 2; s++) {
            const int pA = wm * 32 + s * 16 + gid;
            const int bA = (pA < bound) ? bstart : b1;
            const int bB = (pA + 8 < bound) ? bstart : b1;
#pragma unroll
            for (int t = 0; t < 8; t++) {
                const int jA = wn * 64 + t * 8 + 2 * tig;
                float* d = acc[s][t];
                float x0 = rowdy_f(d[0] + bvec[jA],     avec[jA],     wvec[jA]);
                float x1 = rowdy_f(d[1] + bvec[jA + 1], avec[jA + 1], wvec[jA + 1]);
                float x2 = rowdy_f(d[2] + bvec[jA],     avec[jA],     wvec[jA]);
                float x3 = rowdy_f(d[3] + bvec[jA + 1], avec[jA + 1], wvec[jA + 1]);
                if (l < 3) {
                    const float* gA = &g_gate[(l * NB + bA) * HID];
                    const float* gB = &g_gate[(l * NB + bB) * HID];
                    x0 *= __ldg(&gA[jA]); x1 *= __ldg(&gA[jA + 1]);
                    x2 *= __ldg(&gB[jA]); x3 *= __ldg(&gB[jA + 1]);
                    store_x(su, pA,     jA, x0, x1);
                    store_x(su, pA + 8, jA, x2, x3);
                } else {
                    scr[jA * 128 + pA]           = x0;
                    scr[(jA + 1) * 128 + pA]     = x1;
                    scr[jA * 128 + pA + 8]       = x2;
                    scr[(jA + 1) * 128 + pA + 8] = x3;
                }
            }
        }
        __syncthreads();
    }

    // ---- folded final: out[p][o] = c[b][o] + sum_g x[p][g] * M'[b][g][o] ----
    {
        float* part = (float*)(smem + SM_PART);    // [5][2][128]
        const int p = tid & 127;
        const int q = tid >> 7;
        const int b = (p < bound) ? bstart : b1;
        float o0 = 0.f, o1 = 0.f, o2 = 0.f, o3 = 0.f, o4 = 0.f;
        const float4* Mb = (const float4*)&g_M[b * HID * 8];
#pragma unroll 8
        for (int g = q * 64; g < q * 64 + 64; g++) {
            float v   = scr[g * 128 + p];
            float4 m0 = __ldg(&Mb[g * 2 + 0]);
            float4 m1 = __ldg(&Mb[g * 2 + 1]);
            o0 += v * m0.x; o1 += v * m0.y; o2 += v * m0.z; o3 += v * m0.w;
            o4 += v * m1.x;
        }
        part[(0 * 2 + q) * 128 + p] = o0;
        part[(1 * 2 + q) * 128 + p] = o1;
        part[(2 * 2 + q) * 128 + p] = o2;
        part[(3 * 2 + q) * 128 + p] = o3;
        part[(4 * 2 + q) * 128 + p] = o4;
        __syncthreads();
        if (tid < BP) {
            const int gp = p0 + tid;
            const int b2 = (tid < bound) ? bstart : b1;
            float* op = out + (size_t)gp * OUTD;
#pragma unroll
            for (int o = 0; o < OUTD; o++)
                op[o] = g_c[b2 * 8 + o]
                      + part[(o * 2 + 0) * 128 + tid]
                      + part[(o * 2 + 1) * 128 + tid];
        }
    }
}

// ---------------------------------------------------------------------------
extern "C" void kernel_launch(void* const* d_in, const int* in_sizes, int n_in,
                              void* d_out, int out_size)
{
    const float* coords = (const float*)d_in[0];
    const float* sdf    = (const float*)d_in[1];
    const float* params = (const float*)d_in[2];
    const float* Wb0    = (const float*)d_in[3];
    const float* bb0    = (const float*)d_in[4];
    const float* Wb     = (const float*)d_in[5];
    const float* bb     = (const float*)d_in[6];
    const float* Wbf    = (const float*)d_in[7];
    const float* bbf    = (const float*)d_in[8];
    const float* ab     = (const float*)d_in[9];
    const float* wb     = (const float*)d_in[10];
    const float* Wt0    = (const float*)d_in[11];
    const float* bt0    = (const float*)d_in[12];
    const float* Wt     = (const float*)d_in[13];
    const float* bt     = (const float*)d_in[14];
    const float* Wtf    = (const float*)d_in[15];
    const float* btf    = (const float*)d_in[16];
    const float* at     = (const float*)d_in[17];
    const float* wt     = (const float*)d_in[18];
    float* out = (float*)d_out;

    static int smem_set = 0;
    if (!smem_set) {
        cudaFuncSetAttribute(trunk_kernel,
                             cudaFuncAttributeMaxDynamicSharedMemorySize,
                             SM_TOTAL);
        smem_set = 1;
    }

    branch_prep_kernel<<<NB + 96, 512>>>(params, Wb0, bb0, Wb, bb, Wbf, bbf,
                                         ab, wb, Wtf, btf, Wt);
    trunk_kernel<<<LTOT / BP, 256, SM_TOTAL>>>(coords, sdf, Wt0, bt0,
                                               bt, at, wt, out);
}

// round 11
// speedup vs baseline: 1.1257x; 1.1257x over previous
#include <cuda_runtime.h>
#include <cuda_fp16.h>
#include <cstdint>

#define HID   128
#define NB    16
#define NPTS  10000
#define OUTD  5
#define LTOT  160000
#define BP    128

// ---------------- device scratch (no allocation allowed) -------------------
__device__ float g_gate[4 * NB * HID];
__device__ float g_M[NB * HID * 8];      // gate3-folded Wtf@bc^T, padded 8
__device__ float g_c[NB * 8];
// Pre-transposed fp16-split pre-swizzled weights:
// [l][half][plane: wh/wl][n=128][k=64] fp16
__device__ __align__(16) __half g_WT[6 * 16384];

// SMEM byte map (per CTA, dynamic):
//  [0,32768)       XA plane [128 p][128 k] fp16, row 256B, swz ((p&7)<<4)
//  [32768,65536)   XB plane (double buffer)
//  [65536,98304)   W stage half-K: [plane][128 n][64 k] fp16
//  [98304,106496)  params (2048 floats)
//  L3 fp32 scratch aliases [32768,98304) (XB+W); partials alias XA.
#define SM_XA  0
#define SM_XB  32768
#define SM_W   65536
#define SM_PAR 98304
#define SM_TOTAL 106496
#define PAR_BT0 0
#define PAR_W0  128
#define PAR_AT  640
#define PAR_WT  1152
#define PAR_BT  1664

__device__ __forceinline__ float rowdy_f(float t, float a, float w) {
    float th; asm("tanh.approx.f32 %0, %1;" : "=f"(th) : "f"(t));
    return th + a * __sinf(w * t);
}
__device__ __forceinline__ void cp_async16(uint32_t smem_dst, const void* gmem_src) {
    asm volatile("cp.async.cg.shared.global [%0], [%1], 16;" :: "r"(smem_dst), "l"(gmem_src));
}
__device__ __forceinline__ void ldsm4(uint32_t* r, uint32_t a) {
    asm volatile("ldmatrix.sync.aligned.m8n8.x4.shared.b16 {%0,%1,%2,%3}, [%4];"
                 : "=r"(r[0]), "=r"(r[1]), "=r"(r[2]), "=r"(r[3]) : "r"(a));
}
__device__ __forceinline__ void mma16816(float* d, const uint32_t* a,
                                         uint32_t b0, uint32_t b1) {
    asm volatile(
        "mma.sync.aligned.m16n8k16.row.col.f32.f16.f16.f32 "
        "{%0,%1,%2,%3}, {%4,%5,%6,%7}, {%8,%9}, {%0,%1,%2,%3};"
        : "+f"(d[0]), "+f"(d[1]), "+f"(d[2]), "+f"(d[3])
        : "r"(a[0]), "r"(a[1]), "r"(a[2]), "r"(a[3]), "r"(b0), "r"(b1));
}
// pack (x0,x1) to fp16x2 and store to X plane at byte base xb
__device__ __forceinline__ void store_x(uint32_t su, uint32_t xb, int p, int j,
                                        float x0, float x1) {
    uint32_t hx;
    asm("cvt.rn.f16x2.f32 %0, %1, %2;" : "=r"(hx) : "f"(x1), "f"(x0));
    uint32_t off = (uint32_t)(p * 256) + (uint32_t)((j * 2) ^ ((p & 7) << 4));
    asm volatile("st.shared.b32 [%0], %1;" :: "r"(su + xb + off), "r"(hx));
}
// stage one half-K of split weights (32KB) and commit
__device__ __forceinline__ void stage_W(uint32_t su, const __half* src, int tid) {
#pragma unroll
    for (int i = 0; i < 8; i++)
        cp_async16(su + SM_W + (uint32_t)(tid + i * 256) * 16,
                   (const char*)src + (tid + i * 256) * 16);
    asm volatile("cp.async.commit_group;");
}

// ---------------------------------------------------------------------------
// Branch MLP + gates + folded matrices (blocks 0..15) and weight prep
// (blocks 16..111).
// ---------------------------------------------------------------------------
__global__ void __launch_bounds__(512, 1) branch_prep_kernel(
    const float* __restrict__ params, const float* __restrict__ Wb0,
    const float* __restrict__ bb0,    const float* __restrict__ Wb,
    const float* __restrict__ bb,     const float* __restrict__ Wbf,
    const float* __restrict__ bbf,    const float* __restrict__ ab,
    const float* __restrict__ wb,     const float* __restrict__ Wtf,
    const float* __restrict__ btf,    const float* __restrict__ Wt)
{
    const int tid = threadIdx.x;

    if (blockIdx.x >= NB) {
        int base = (blockIdx.x - NB) * 512 + tid;
#pragma unroll
        for (int r = 0; r < 2; r++) {
            int idx = base + r * 49152;
            int k     = idx & 63;
            int n     = (idx >> 6) & 127;
            int plane = (idx >> 13) & 1;
            int lh    = idx >> 14;            // l*2 + h
            int l = lh >> 1, h = lh & 1;
            float w = Wt[l * 16384 + (h * 64 + k) * 128 + n];
            __half wh = __float2half_rn(w);
            __half val;
            if (plane == 0) val = wh;
            else            val = __float2half_rn(w - __half2float(wh));
            g_WT[lh * 16384 + plane * 8192 + n * 64 + (k ^ ((n & 7) << 3))] = val;
        }
        return;
    }

    const int b = blockIdx.x;
    const int j = tid & 127;
    const int q = tid >> 7;

    __shared__ float sh_h[HID];
    __shared__ float sh_part[4 * HID];
    __shared__ float sh_bc[OUTD][HID];
    __shared__ float sh_p[8];

    if (tid < 6) sh_p[tid] = params[b * 6 + tid];
    __syncthreads();

    float h = 0.f, gate = 0.f;
    if (q == 0) {
        float t = bb0[j];
#pragma unroll
        for (int k = 0; k < 6; k++) t += sh_p[k] * Wb0[k * HID + j];
        h = tanhf(t) + ab[j] * __sinf(wb[j] * t);
        gate = h;
        sh_h[j] = h;
        g_gate[(0 * NB + b) * HID + j] = gate;
    }
    __syncthreads();

    for (int i = 0; i < 3; i++) {
        const float* W = Wb + i * HID * HID;
        float tp = 0.f;
#pragma unroll 8
        for (int k = q * 32; k < q * 32 + 32; k++) tp += sh_h[k] * W[k * HID + j];
        sh_part[q * HID + j] = tp;
        __syncthreads();
        if (q == 0) {
            float t2 = bb[i * HID + j] + sh_part[j] + sh_part[HID + j]
                     + sh_part[2 * HID + j] + sh_part[3 * HID + j];
            h = tanhf(t2) + ab[(i + 1) * HID + j] * __sinf(wb[(i + 1) * HID + j] * t2);
            sh_h[j] = h;
            gate += h;
            g_gate[((i + 1) * NB + b) * HID + j] = gate;
        }
        __syncthreads();
    }

    {
        float tb[OUTD] = {0.f, 0.f, 0.f, 0.f, 0.f};
#pragma unroll 4
        for (int k = q * 32; k < q * 32 + 32; k++) {
            float hv = sh_h[k];
#pragma unroll
            for (int o = 0; o < OUTD; o++)
                tb[o] += hv * Wbf[k * (HID * OUTD) + o * HID + j];
        }
#pragma unroll
        for (int o = 0; o < OUTD; o++) {
            sh_part[q * HID + j] = tb[o];
            __syncthreads();
            if (q == 0)
                sh_bc[o][j] = bbf[o * HID + j] + sh_part[j] + sh_part[HID + j]
                            + sh_part[2 * HID + j] + sh_part[3 * HID + j];
            __syncthreads();
        }
    }

    {
        float am[OUTD] = {0.f, 0.f, 0.f, 0.f, 0.f};
#pragma unroll 4
        for (int hh = q * 32; hh < q * 32 + 32; hh++) {
            float w = __ldg(&Wtf[j * HID + hh]);
#pragma unroll
            for (int o = 0; o < OUTD; o++) am[o] += w * sh_bc[o][hh];
        }
#pragma unroll
        for (int o = 0; o < OUTD; o++) {
            sh_part[q * HID + j] = am[o];
            __syncthreads();
            if (q == 0)
                g_M[(b * HID + j) * 8 + o] = gate *
                    (sh_part[j] + sh_part[HID + j] + sh_part[2 * HID + j] + sh_part[3 * HID + j]);
            __syncthreads();
        }
        if (q == 0) { g_M[(b * HID + j) * 8 + 5] = 0.f;
                      g_M[(b * HID + j) * 8 + 6] = 0.f;
                      g_M[(b * HID + j) * 8 + 7] = 0.f; }
    }
    if (tid < OUTD) {
        float c = 0.f;
#pragma unroll 8
        for (int hh = 0; hh < HID; hh++) c += btf[hh] * sh_bc[tid][hh];
        g_c[b * 8 + tid] = c;
    }
    if (tid >= OUTD && tid < 8) g_c[b * 8 + tid] = 0.f;
}

// ---------------------------------------------------------------------------
// Trunk: HMMA fp16 2-term W-split. 256 threads, 8 warps as 2M x 4N (warp
// tile 64x32 -> halved B-fragment redundancy). X double-buffered.
// ---------------------------------------------------------------------------
__global__ void __launch_bounds__(256, 2)
trunk_kernel(const float* __restrict__ coords, const float* __restrict__ sdf,
             const float* __restrict__ Wt0,    const float* __restrict__ bt0,
             const float* __restrict__ bt,     const float* __restrict__ at,
             const float* __restrict__ wt,     float* __restrict__ out)
{
    extern __shared__ char smem[];
    float* sp  = (float*)(smem + SM_PAR);
    float* scr = (float*)(smem + SM_XB);        // L3 fp32 scratch: XB+W (64KB)
    float* part = (float*)smem;                  // final partials alias XA
    const uint32_t su = (uint32_t)__cvta_generic_to_shared(smem);

    const int tid  = threadIdx.x;
    const int lane = tid & 31;
    const int wid  = tid >> 5;
    const int wm   = wid & 1;                    // M half 0..1 (64 rows)
    const int wn   = wid >> 1;                   // N quarter 0..3 (32 cols)
    const int la7  = lane & 7;
    const int lb3  = (lane >> 3) & 1;
    const int lb4  = lane >> 4;
    const int gid  = lane >> 2;
    const int tig  = lane & 3;
    const uint32_t swz = (uint32_t)la7 << 4;

    const int p0     = blockIdx.x * BP;
    const int bstart = p0 / NPTS;
    const int bound  = (bstart + 1) * NPTS - p0;
    const int b1     = (bstart + 1 < NB) ? bstart + 1 : NB - 1;

    // stage layer-1 W half0 immediately
    stage_W(su, g_WT, tid);

    if (tid < 128) sp[PAR_BT0 + tid] = bt0[tid];
    for (int i = tid; i < 512; i += 256) {
        sp[PAR_W0 + i] = Wt0[i];
        sp[PAR_AT + i] = at[i];
        sp[PAR_WT + i] = wt[i];
    }
    for (int i = tid; i < 384; i += 256) sp[PAR_BT + i] = bt[i];
    __syncthreads();

    // ---- layer 0: 2 threads per point, 64 features each; writes XA ----
    {
        const int p  = tid & 127;
        const int jh = tid >> 7;
        const int gp = p0 + p;
        float c0 = coords[gp * 3 + 0];
        float c1 = coords[gp * 3 + 1];
        float c2 = coords[gp * 3 + 2];
        float c3 = sdf[gp];
        const int bpt = (p < bound) ? bstart : b1;
        const float* gv = &g_gate[(0 * NB + bpt) * HID];
#pragma unroll 4
        for (int i = 0; i < 32; i++) {
            int j = jh * 64 + 2 * i;
            float t0 = sp[PAR_BT0 + j]
                     + c0 * sp[PAR_W0 + j]       + c1 * sp[PAR_W0 + 128 + j]
                     + c2 * sp[PAR_W0 + 256 + j] + c3 * sp[PAR_W0 + 384 + j];
            float t1 = sp[PAR_BT0 + j + 1]
                     + c0 * sp[PAR_W0 + j + 1]       + c1 * sp[PAR_W0 + 128 + j + 1]
                     + c2 * sp[PAR_W0 + 256 + j + 1] + c3 * sp[PAR_W0 + 384 + j + 1];
            float x0 = rowdy_f(t0, sp[PAR_AT + j], sp[PAR_WT + j]) * __ldg(&gv[j]);
            float x1 = rowdy_f(t1, sp[PAR_AT + j + 1], sp[PAR_WT + j + 1]) * __ldg(&gv[j + 1]);
            store_x(su, SM_XA, p, j, x0, x1);
        }
    }

    float acc[4][4][4];                          // [s: M 16-tile][t=q*2+u][4]

    // ---- layers 1..3 ----
    for (int l = 1; l <= 3; l++) {
        const uint32_t xr = (l == 2) ? (uint32_t)SM_XB : (uint32_t)SM_XA;
        const uint32_t xw = (l == 1) ? (uint32_t)SM_XB : (uint32_t)SM_XA;

        asm volatile("cp.async.wait_group 0;");
        __syncthreads();       // W half0 staged + X writes visible

#pragma unroll
        for (int s = 0; s < 4; s++)
#pragma unroll
            for (int t = 0; t < 4; t++)
#pragma unroll
                for (int i = 0; i < 4; i++) acc[s][t][i] = 0.f;

        for (int half = 0; half < 2; half++) {
#pragma unroll
            for (int kl = 0; kl < 4; kl++) {
                const int ks = half * 4 + kl;
                // batch all LDSM for this k-step (MLP), then dense MMA
                uint32_t a[4][4];
#pragma unroll
                for (int s = 0; s < 4; s++) {
                    uint32_t arow = (uint32_t)(wm * 64 + s * 16 + la7 + 8 * lb3);
                    uint32_t aoff = ((uint32_t)(ks * 32 + 16 * lb4)) ^ swz;
                    ldsm4(a[s], su + xr + arow * 256 + aoff);
                }
                uint32_t bh[2][4], bl[2][4];
#pragma unroll
                for (int q = 0; q < 2; q++) {
                    uint32_t nrow = (uint32_t)(wn * 32 + q * 16 + la7 + 8 * lb4);
                    uint32_t boff = ((uint32_t)(kl * 32 + 16 * lb3)) ^ swz;
                    ldsm4(bh[q], su + SM_W + nrow * 128 + boff);
                    ldsm4(bl[q], su + SM_W + 16384 + nrow * 128 + boff);
                }
#pragma unroll
                for (int s = 0; s < 4; s++)
#pragma unroll
                    for (int q = 0; q < 2; q++)
#pragma unroll
                        for (int u = 0; u < 2; u++) {
                            float* d = acc[s][q * 2 + u];
                            mma16816(d, a[s], bh[q][2 * u], bh[q][2 * u + 1]);
                            mma16816(d, a[s], bl[q][2 * u], bl[q][2 * u + 1]);
                        }
            }
            __syncthreads();                 // this half's W reads done
            if (half == 0) {
                stage_W(su, g_WT + ((l - 1) * 2 + 1) * 16384, tid);
                asm volatile("cp.async.wait_group 0;");
                __syncthreads();
            }
        }
        // post-h1 sync above covers W reads; X reads also done (xr != xw for
        // l<3; for l==3 scr overlaps W+XB, xr=XA — safe after that sync)

        if (l < 3) stage_W(su, g_WT + (l * 2) * 16384, tid);  // overlaps epilogue

        const float* bvec = &sp[PAR_BT + (l - 1) * 128];
        const float* avec = &sp[PAR_AT + l * 128];
        const float* wvec = &sp[PAR_WT + l * 128];
#pragma unroll
        for (int s = 0; s < 4; s++) {
            const int pA = wm * 64 + s * 16 + gid;
            const int bA = (pA < bound) ? bstart : b1;
            const int bB = (pA + 8 < bound) ? bstart : b1;
#pragma unroll
            for (int t = 0; t < 4; t++) {
                const int jA = wn * 32 + t * 8 + 2 * tig;
                float* d = acc[s][t];
                float x0 = rowdy_f(d[0] + bvec[jA],     avec[jA],     wvec[jA]);
                float x1 = rowdy_f(d[1] + bvec[jA + 1], avec[jA + 1], wvec[jA + 1]);
                float x2 = rowdy_f(d[2] + bvec[jA],     avec[jA],     wvec[jA]);
                float x3 = rowdy_f(d[3] + bvec[jA + 1], avec[jA + 1], wvec[jA + 1]);
                if (l < 3) {
                    const float* gA = &g_gate[(l * NB + bA) * HID];
                    const float* gB = &g_gate[(l * NB + bB) * HID];
                    x0 *= __ldg(&gA[jA]); x1 *= __ldg(&gA[jA + 1]);
                    x2 *= __ldg(&gB[jA]); x3 *= __ldg(&gB[jA + 1]);
                    store_x(su, xw, pA,     jA, x0, x1);
                    store_x(su, xw, pA + 8, jA, x2, x3);
                } else {
                    scr[jA * 128 + pA]           = x0;
                    scr[(jA + 1) * 128 + pA]     = x1;
                    scr[jA * 128 + pA + 8]       = x2;
                    scr[(jA + 1) * 128 + pA + 8] = x3;
                }
            }
        }
        if (l == 3) __syncthreads();   // scr complete before contraction
        // l<3: no trailing sync; next layer's top sync orders xw writes
    }

    // ---- folded final: out[p][o] = c[b][o] + sum_g x[p][g] * M'[b][g][o] ----
    {
        const int p = tid & 127;
        const int q = tid >> 7;
        const int b = (p < bound) ? bstart : b1;
        float o0 = 0.f, o1 = 0.f, o2 = 0.f, o3 = 0.f, o4 = 0.f;
        const float4* Mb = (const float4*)&g_M[b * HID * 8];
#pragma unroll 8
        for (int g = q * 64; g < q * 64 + 64; g++) {
            float v   = scr[g * 128 + p];
            float4 m0 = __ldg(&Mb[g * 2 + 0]);
            float4 m1 = __ldg(&Mb[g * 2 + 1]);
            o0 += v * m0.x; o1 += v * m0.y; o2 += v * m0.z; o3 += v * m0.w;
            o4 += v * m1.x;
        }
        part[(0 * 2 + q) * 128 + p] = o0;
        part[(1 * 2 + q) * 128 + p] = o1;
        part[(2 * 2 + q) * 128 + p] = o2;
        part[(3 * 2 + q) * 128 + p] = o3;
        part[(4 * 2 + q) * 128 + p] = o4;
        __syncthreads();
        if (tid < BP) {
            const int gp = p0 + tid;
            const int b2 = (tid < bound) ? bstart : b1;
            float* op = out + (size_t)gp * OUTD;
#pragma unroll
            for (int o = 0; o < OUTD; o++)
                op[o] = g_c[b2 * 8 + o]
                      + part[(o * 2 + 0) * 128 + tid]
                      + part[(o * 2 + 1) * 128 + tid];
        }
    }
}

// ---------------------------------------------------------------------------
extern "C" void kernel_launch(void* const* d_in, const int* in_sizes, int n_in,
                              void* d_out, int out_size)
{
    const float* coords = (const float*)d_in[0];
    const float* sdf    = (const float*)d_in[1];
    const float* params = (const float*)d_in[2];
    const float* Wb0    = (const float*)d_in[3];
    const float* bb0    = (const float*)d_in[4];
    const float* Wb     = (const float*)d_in[5];
    const float* bb     = (const float*)d_in[6];
    const float* Wbf    = (const float*)d_in[7];
    const float* bbf    = (const float*)d_in[8];
    const float* ab     = (const float*)d_in[9];
    const float* wb     = (const float*)d_in[10];
    const float* Wt0    = (const float*)d_in[11];
    const float* bt0    = (const float*)d_in[12];
    const float* Wt     = (const float*)d_in[13];
    const float* bt     = (const float*)d_in[14];
    const float* Wtf    = (const float*)d_in[15];
    const float* btf    = (const float*)d_in[16];
    const float* at     = (const float*)d_in[17];
    const float* wt     = (const float*)d_in[18];
    float* out = (float*)d_out;

    static int smem_set = 0;
    if (!smem_set) {
        cudaFuncSetAttribute(trunk_kernel,
                             cudaFuncAttributeMaxDynamicSharedMemorySize,
                             SM_TOTAL);
        smem_set = 1;
    }

    branch_prep_kernel<<<NB + 96, 512>>>(params, Wb0, bb0, Wb, bb, Wbf, bbf,
                                         ab, wb, Wtf, btf, Wt);
    trunk_kernel<<<LTOT / BP, 256, SM_TOTAL>>>(coords, sdf, Wt0, bt0,
                                               bt, at, wt, out);
}

// round 12
// speedup vs baseline: 1.1578x; 1.0286x over previous
#include <cuda_runtime.h>
#include <cuda_fp16.h>
#include <cstdint>

#define HID   128
#define NB    16
#define NPTS  10000
#define OUTD  5
#define LTOT  160000
#define BP    128

// ---------------- device scratch (no allocation allowed) -------------------
__device__ float g_gate[4 * NB * HID];
__device__ float g_M[NB * HID * 8];      // gate3-folded Wtf@bc^T, padded 8
__device__ float g_c[NB * 8];
// Pre-transposed fp16-split pre-swizzled weights:
// [l][half][plane: wh/wl][n=128][k=64] fp16
__device__ __align__(16) __half g_WT[6 * 16384];

// SMEM byte map (per CTA, dynamic):
//  [0,32768)       X plane [128 p][128 k] fp16, row 256B, swz ((p&7)<<4)
//  [32768,65536)   WA: half-K weights [plane][128 n][64 k] fp16
//  [65536,98304)   WB: half-K weights (double buffer)
//  [98304,106496)  params (2048 floats)
//  L3 fp32 scratch aliases [32768,98304) (WA+WB); partials alias X.
#define SM_X   0
#define SM_WA  32768
#define SM_WB  65536
#define SM_PAR 98304
#define SM_TOTAL 106496
#define PAR_BT0 0
#define PAR_W0  128
#define PAR_AT  640
#define PAR_WT  1152
#define PAR_BT  1664

__device__ __forceinline__ float rowdy_f(float t, float a, float w) {
    float th; asm("tanh.approx.f32 %0, %1;" : "=f"(th) : "f"(t));
    return th + a * __sinf(w * t);
}
__device__ __forceinline__ void cp_async16(uint32_t smem_dst, const void* gmem_src) {
    asm volatile("cp.async.cg.shared.global [%0], [%1], 16;" :: "r"(smem_dst), "l"(gmem_src));
}
__device__ __forceinline__ void ldsm4(uint32_t* r, uint32_t a) {
    asm volatile("ldmatrix.sync.aligned.m8n8.x4.shared.b16 {%0,%1,%2,%3}, [%4];"
                 : "=r"(r[0]), "=r"(r[1]), "=r"(r[2]), "=r"(r[3]) : "r"(a));
}
__device__ __forceinline__ void mma16816(float* d, const uint32_t* a,
                                         uint32_t b0, uint32_t b1) {
    asm volatile(
        "mma.sync.aligned.m16n8k16.row.col.f32.f16.f16.f32 "
        "{%0,%1,%2,%3}, {%4,%5,%6,%7}, {%8,%9}, {%0,%1,%2,%3};"
        : "+f"(d[0]), "+f"(d[1]), "+f"(d[2]), "+f"(d[3])
        : "r"(a[0]), "r"(a[1]), "r"(a[2]), "r"(a[3]), "r"(b0), "r"(b1));
}
// pack (x0,x1) to fp16x2 and store to X plane
__device__ __forceinline__ void store_x(uint32_t su, int p, int j,
                                        float x0, float x1) {
    uint32_t hx;
    asm("cvt.rn.f16x2.f32 %0, %1, %2;" : "=r"(hx) : "f"(x1), "f"(x0));
    uint32_t off = (uint32_t)(p * 256) + (uint32_t)((j * 2) ^ ((p & 7) << 4));
    asm volatile("st.shared.b32 [%0], %1;" :: "r"(su + SM_X + off), "r"(hx));
}
// stage one half-K of split weights (32KB) into wbase and commit
__device__ __forceinline__ void stage_W(uint32_t wbase, const __half* src, int tid) {
#pragma unroll
    for (int i = 0; i < 8; i++)
        cp_async16(wbase + (uint32_t)(tid + i * 256) * 16,
                   (const char*)src + (tid + i * 256) * 16);
    asm volatile("cp.async.commit_group;");
}

// ---------------------------------------------------------------------------
// Branch MLP + gates + folded matrices (blocks 0..15) and weight prep
// (blocks 16..111).
// ---------------------------------------------------------------------------
__global__ void __launch_bounds__(512, 1) branch_prep_kernel(
    const float* __restrict__ params, const float* __restrict__ Wb0,
    const float* __restrict__ bb0,    const float* __restrict__ Wb,
    const float* __restrict__ bb,     const float* __restrict__ Wbf,
    const float* __restrict__ bbf,    const float* __restrict__ ab,
    const float* __restrict__ wb,     const float* __restrict__ Wtf,
    const float* __restrict__ btf,    const float* __restrict__ Wt)
{
    const int tid = threadIdx.x;

    if (blockIdx.x >= NB) {
        int base = (blockIdx.x - NB) * 512 + tid;
#pragma unroll
        for (int r = 0; r < 2; r++) {
            int idx = base + r * 49152;
            int k     = idx & 63;
            int n     = (idx >> 6) & 127;
            int plane = (idx >> 13) & 1;
            int lh    = idx >> 14;            // l*2 + h
            int l = lh >> 1, h = lh & 1;
            float w = Wt[l * 16384 + (h * 64 + k) * 128 + n];
            __half wh = __float2half_rn(w);
            __half val;
            if (plane == 0) val = wh;
            else            val = __float2half_rn(w - __half2float(wh));
            g_WT[lh * 16384 + plane * 8192 + n * 64 + (k ^ ((n & 7) << 3))] = val;
        }
        return;
    }

    const int b = blockIdx.x;
    const int j = tid & 127;
    const int q = tid >> 7;

    __shared__ float sh_h[HID];
    __shared__ float sh_part[4 * HID];
    __shared__ float sh_bc[OUTD][HID];
    __shared__ float sh_p[8];

    if (tid < 6) sh_p[tid] = params[b * 6 + tid];
    __syncthreads();

    float h = 0.f, gate = 0.f;
    if (q == 0) {
        float t = bb0[j];
#pragma unroll
        for (int k = 0; k < 6; k++) t += sh_p[k] * Wb0[k * HID + j];
        h = tanhf(t) + ab[j] * __sinf(wb[j] * t);
        gate = h;
        sh_h[j] = h;
        g_gate[(0 * NB + b) * HID + j] = gate;
    }
    __syncthreads();

    for (int i = 0; i < 3; i++) {
        const float* W = Wb + i * HID * HID;
        float tp = 0.f;
#pragma unroll 8
        for (int k = q * 32; k < q * 32 + 32; k++) tp += sh_h[k] * W[k * HID + j];
        sh_part[q * HID + j] = tp;
        __syncthreads();
        if (q == 0) {
            float t2 = bb[i * HID + j] + sh_part[j] + sh_part[HID + j]
                     + sh_part[2 * HID + j] + sh_part[3 * HID + j];
            h = tanhf(t2) + ab[(i + 1) * HID + j] * __sinf(wb[(i + 1) * HID + j] * t2);
            sh_h[j] = h;
            gate += h;
            g_gate[((i + 1) * NB + b) * HID + j] = gate;
        }
        __syncthreads();
    }

    {
        float tb[OUTD] = {0.f, 0.f, 0.f, 0.f, 0.f};
#pragma unroll 4
        for (int k = q * 32; k < q * 32 + 32; k++) {
            float hv = sh_h[k];
#pragma unroll
            for (int o = 0; o < OUTD; o++)
                tb[o] += hv * Wbf[k * (HID * OUTD) + o * HID + j];
        }
#pragma unroll
        for (int o = 0; o < OUTD; o++) {
            sh_part[q * HID + j] = tb[o];
            __syncthreads();
            if (q == 0)
                sh_bc[o][j] = bbf[o * HID + j] + sh_part[j] + sh_part[HID + j]
                            + sh_part[2 * HID + j] + sh_part[3 * HID + j];
            __syncthreads();
        }
    }

    {
        float am[OUTD] = {0.f, 0.f, 0.f, 0.f, 0.f};
#pragma unroll 4
        for (int hh = q * 32; hh < q * 32 + 32; hh++) {
            float w = __ldg(&Wtf[j * HID + hh]);
#pragma unroll
            for (int o = 0; o < OUTD; o++) am[o] += w * sh_bc[o][hh];
        }
#pragma unroll
        for (int o = 0; o < OUTD; o++) {
            sh_part[q * HID + j] = am[o];
            __syncthreads();
            if (q == 0)
                g_M[(b * HID + j) * 8 + o] = gate *
                    (sh_part[j] + sh_part[HID + j] + sh_part[2 * HID + j] + sh_part[3 * HID + j]);
            __syncthreads();
        }
        if (q == 0) { g_M[(b * HID + j) * 8 + 5] = 0.f;
                      g_M[(b * HID + j) * 8 + 6] = 0.f;
                      g_M[(b * HID + j) * 8 + 7] = 0.f; }
    }
    if (tid < OUTD) {
        float c = 0.f;
#pragma unroll 8
        for (int hh = 0; hh < HID; hh++) c += btf[hh] * sh_bc[tid][hh];
        g_c[b * 8 + tid] = c;
    }
    if (tid >= OUTD && tid < 8) g_c[b * 8 + tid] = 0.f;
}

// ---------------------------------------------------------------------------
// Trunk: HMMA fp16 2-term W-split, double-buffered W (all cp.async waits land
// on data already in flight during compute). 256 threads, 2M x 4N warp grid.
// ---------------------------------------------------------------------------
__global__ void __launch_bounds__(256, 2)
trunk_kernel(const float* __restrict__ coords, const float* __restrict__ sdf,
             const float* __restrict__ Wt0,    const float* __restrict__ bt0,
             const float* __restrict__ bt,     const float* __restrict__ at,
             const float* __restrict__ wt,     float* __restrict__ out)
{
    extern __shared__ char smem[];
    float* sp   = (float*)(smem + SM_PAR);
    float* scr  = (float*)(smem + SM_WA);       // L3 fp32 scratch: WA+WB (64KB)
    float* part = (float*)smem;                  // final partials alias X
    const uint32_t su = (uint32_t)__cvta_generic_to_shared(smem);

    const int tid  = threadIdx.x;
    const int lane = tid & 31;
    const int wid  = tid >> 5;
    const int wm   = wid & 1;                    // M half (64 rows)
    const int wn   = wid >> 1;                   // N quarter (32 cols)
    const int la7  = lane & 7;
    const int lb3  = (lane >> 3) & 1;
    const int lb4  = lane >> 4;
    const int gid  = lane >> 2;
    const int tig  = lane & 3;
    const uint32_t swz = (uint32_t)la7 << 4;

    const int p0     = blockIdx.x * BP;
    const int bstart = p0 / NPTS;
    const int bound  = (bstart + 1) * NPTS - p0;
    const int b1     = (bstart + 1 < NB) ? bstart + 1 : NB - 1;

    // stage layer-1 h0 into WA immediately (hidden under layer 0)
    stage_W(su + SM_WA, g_WT, tid);

    if (tid < 128) sp[PAR_BT0 + tid] = bt0[tid];
    for (int i = tid; i < 512; i += 256) {
        sp[PAR_W0 + i] = Wt0[i];
        sp[PAR_AT + i] = at[i];
        sp[PAR_WT + i] = wt[i];
    }
    for (int i = tid; i < 384; i += 256) sp[PAR_BT + i] = bt[i];
    __syncthreads();

    // ---- layer 0: 2 threads per point, 64 features each; writes X ----
    {
        const int p  = tid & 127;
        const int jh = tid >> 7;
        const int gp = p0 + p;
        float c0 = coords[gp * 3 + 0];
        float c1 = coords[gp * 3 + 1];
        float c2 = coords[gp * 3 + 2];
        float c3 = sdf[gp];
        const int bpt = (p < bound) ? bstart : b1;
        const float* gv = &g_gate[(0 * NB + bpt) * HID];
#pragma unroll 4
        for (int i = 0; i < 32; i++) {
            int j = jh * 64 + 2 * i;
            float t0 = sp[PAR_BT0 + j]
                     + c0 * sp[PAR_W0 + j]       + c1 * sp[PAR_W0 + 128 + j]
                     + c2 * sp[PAR_W0 + 256 + j] + c3 * sp[PAR_W0 + 384 + j];
            float t1 = sp[PAR_BT0 + j + 1]
                     + c0 * sp[PAR_W0 + j + 1]       + c1 * sp[PAR_W0 + 128 + j + 1]
                     + c2 * sp[PAR_W0 + 256 + j + 1] + c3 * sp[PAR_W0 + 384 + j + 1];
            float x0 = rowdy_f(t0, sp[PAR_AT + j], sp[PAR_WT + j]) * __ldg(&gv[j]);
            float x1 = rowdy_f(t1, sp[PAR_AT + j + 1], sp[PAR_WT + j + 1]) * __ldg(&gv[j + 1]);
            store_x(su, p, j, x0, x1);
        }
    }

    float acc[4][4][4];                          // [s: M 16-tile][t=q*2+u][4]

    // ---- layers 1..3 ----
    for (int l = 1; l <= 3; l++) {
        // commit h1 -> WB; wait only for the OLDER WA group (arrived during
        // previous layer's MMA h1 + epilogue, or layer 0)
        stage_W(su + SM_WB, g_WT + ((l - 1) * 2 + 1) * 16384, tid);
        asm volatile("cp.async.wait_group 1;");
        __syncthreads();       // WA ready + X writes visible

#pragma unroll
        for (int s = 0; s < 4; s++)
#pragma unroll
            for (int t = 0; t < 4; t++)
#pragma unroll
                for (int i = 0; i < 4; i++) acc[s][t][i] = 0.f;

#pragma unroll
        for (int half = 0; half < 2; half++) {
            const uint32_t wb_base = su + (half ? SM_WB : SM_WA);
#pragma unroll
            for (int kl = 0; kl < 4; kl++) {
                const int ks = half * 4 + kl;
                uint32_t a[4][4];
#pragma unroll
                for (int s = 0; s < 4; s++) {
                    uint32_t arow = (uint32_t)(wm * 64 + s * 16 + la7 + 8 * lb3);
                    uint32_t aoff = ((uint32_t)(ks * 32 + 16 * lb4)) ^ swz;
                    ldsm4(a[s], su + SM_X + arow * 256 + aoff);
                }
                uint32_t bh[2][4], bl[2][4];
#pragma unroll
                for (int q = 0; q < 2; q++) {
                    uint32_t nrow = (uint32_t)(wn * 32 + q * 16 + la7 + 8 * lb4);
                    uint32_t boff = ((uint32_t)(kl * 32 + 16 * lb3)) ^ swz;
                    ldsm4(bh[q], wb_base + nrow * 128 + boff);
                    ldsm4(bl[q], wb_base + 16384 + nrow * 128 + boff);
                }
#pragma unroll
                for (int s = 0; s < 4; s++)
#pragma unroll
                    for (int q = 0; q < 2; q++)
#pragma unroll
                        for (int u = 0; u < 2; u++) {
                            float* d = acc[s][q * 2 + u];
                            mma16816(d, a[s], bh[q][2 * u], bh[q][2 * u + 1]);
                            mma16816(d, a[s], bl[q][2 * u], bl[q][2 * u + 1]);
                        }
            }
            if (half == 0) {
                // WB arrived during MMA h0 -> near-zero wait
                asm volatile("cp.async.wait_group 0;");
                __syncthreads();             // also: WA reads done
                if (l < 3) stage_W(su + SM_WA, g_WT + (l * 2) * 16384, tid);
            }
        }
        __syncthreads();       // X + WB reads done (epilogue may overwrite)

        const float* bvec = &sp[PAR_BT + (l - 1) * 128];
        const float* avec = &sp[PAR_AT + l * 128];
        const float* wvec = &sp[PAR_WT + l * 128];
#pragma unroll
        for (int s = 0; s < 4; s++) {
            const int pA = wm * 64 + s * 16 + gid;
            const int bA = (pA < bound) ? bstart : b1;
            const int bB = (pA + 8 < bound) ? bstart : b1;
#pragma unroll
            for (int t = 0; t < 4; t++) {
                const int jA = wn * 32 + t * 8 + 2 * tig;
                float* d = acc[s][t];
                float x0 = rowdy_f(d[0] + bvec[jA],     avec[jA],     wvec[jA]);
                float x1 = rowdy_f(d[1] + bvec[jA + 1], avec[jA + 1], wvec[jA + 1]);
                float x2 = rowdy_f(d[2] + bvec[jA],     avec[jA],     wvec[jA]);
                float x3 = rowdy_f(d[3] + bvec[jA + 1], avec[jA + 1], wvec[jA + 1]);
                if (l < 3) {
                    const float* gA = &g_gate[(l * NB + bA) * HID];
                    const float* gB = &g_gate[(l * NB + bB) * HID];
                    x0 *= __ldg(&gA[jA]); x1 *= __ldg(&gA[jA + 1]);
                    x2 *= __ldg(&gB[jA]); x3 *= __ldg(&gB[jA + 1]);
                    store_x(su, pA,     jA, x0, x1);
                    store_x(su, pA + 8, jA, x2, x3);
                } else {
                    scr[jA * 128 + pA]           = x0;
                    scr[(jA + 1) * 128 + pA]     = x1;
                    scr[jA * 128 + pA + 8]       = x2;
                    scr[(jA + 1) * 128 + pA + 8] = x3;
                }
            }
        }
        if (l == 3) __syncthreads();   // scr complete before contraction
        // l<3: no trailing sync; next layer's top sync orders X writes
    }

    // ---- folded final: out[p][o] = c[b][o] + sum_g x[p][g] * M'[b][g][o] ----
    {
        const int p = tid & 127;
        const int q = tid >> 7;
        const int b = (p < bound) ? bstart : b1;
        float o0 = 0.f, o1 = 0.f, o2 = 0.f, o3 = 0.f, o4 = 0.f;
        const float4* Mb = (const float4*)&g_M[b * HID * 8];
#pragma unroll 8
        for (int g = q * 64; g < q * 64 + 64; g++) {
            float v   = scr[g * 128 + p];
            float4 m0 = __ldg(&Mb[g * 2 + 0]);
            float4 m1 = __ldg(&Mb[g * 2 + 1]);
            o0 += v * m0.x; o1 += v * m0.y; o2 += v * m0.z; o3 += v * m0.w;
            o4 += v * m1.x;
        }
        part[(0 * 2 + q) * 128 + p] = o0;
        part[(1 * 2 + q) * 128 + p] = o1;
        part[(2 * 2 + q) * 128 + p] = o2;
        part[(3 * 2 + q) * 128 + p] = o3;
        part[(4 * 2 + q) * 128 + p] = o4;
        __syncthreads();
        if (tid < BP) {
            const int gp = p0 + tid;
            const int b2 = (tid < bound) ? bstart : b1;
            float* op = out + (size_t)gp * OUTD;
#pragma unroll
            for (int o = 0; o < OUTD; o++)
                op[o] = g_c[b2 * 8 + o]
                      + part[(o * 2 + 0) * 128 + tid]
                      + part[(o * 2 + 1) * 128 + tid];
        }
    }
}

// ---------------------------------------------------------------------------
extern "C" void kernel_launch(void* const* d_in, const int* in_sizes, int n_in,
                              void* d_out, int out_size)
{
    const float* coords = (const float*)d_in[0];
    const float* sdf    = (const float*)d_in[1];
    const float* params = (const float*)d_in[2];
    const float* Wb0    = (const float*)d_in[3];
    const float* bb0    = (const float*)d_in[4];
    const float* Wb     = (const float*)d_in[5];
    const float* bb     = (const float*)d_in[6];
    const float* Wbf    = (const float*)d_in[7];
    const float* bbf    = (const float*)d_in[8];
    const float* ab     = (const float*)d_in[9];
    const float* wb     = (const float*)d_in[10];
    const float* Wt0    = (const float*)d_in[11];
    const float* bt0    = (const float*)d_in[12];
    const float* Wt     = (const float*)d_in[13];
    const float* bt     = (const float*)d_in[14];
    const float* Wtf    = (const float*)d_in[15];
    const float* btf    = (const float*)d_in[16];
    const float* at     = (const float*)d_in[17];
    const float* wt     = (const float*)d_in[18];
    float* out = (float*)d_out;

    static int smem_set = 0;
    if (!smem_set) {
        cudaFuncSetAttribute(trunk_kernel,
                             cudaFuncAttributeMaxDynamicSharedMemorySize,
                             SM_TOTAL);
        smem_set = 1;
    }

    branch_prep_kernel<<<NB + 96, 512>>>(params, Wb0, bb0, Wb, bb, Wbf, bbf,
                                         ab, wb, Wtf, btf, Wt);
    trunk_kernel<<<LTOT / BP, 256, SM_TOTAL>>>(coords, sdf, Wt0, bt0,
                                               bt, at, wt, out);
}

// round 13
// speedup vs baseline: 1.3645x; 1.1785x over previous
#include <cuda_runtime.h>
#include <cuda_fp16.h>
#include <cstdint>

#define HID   128
#define NB    16
#define NPTS  10000
#define OUTD  5
#define LTOT  160000
#define BP    128

// ---------------- device scratch (no allocation allowed) -------------------
__device__ float g_gate[4 * NB * HID];
__device__ float g_M[NB * HID * 8];      // gate3-folded Wtf@bc^T, padded 8
__device__ float g_c[NB * 8];
// Pre-transposed fp16 pre-swizzled weights: [l][n=128][k=128] fp16 (32KB/layer)
__device__ __align__(16) __half g_WT[3 * 16384];

// SMEM byte map (per CTA, dynamic):
//  [0,32768)       X plane [128 p][128 k] fp16, row 256B, swz ((p&7)<<4)
//  [32768,65536)   WA: FULL-layer weights [128 n][128 k] fp16 (row 256B, swz)
//  [65536,98304)   WB: double buffer
//  [98304,106496)  params (2048 floats)
//  L3 fp32 scratch aliases [32768,98304) (WA+WB); partials alias X.
#define SM_X   0
#define SM_WA  32768
#define SM_WB  65536
#define SM_PAR 98304
#define SM_TOTAL 106496
#define PAR_BT0 0
#define PAR_W0  128
#define PAR_AT  640
#define PAR_WT  1152
#define PAR_BT  1664

__device__ __forceinline__ float rowdy_f(float t, float a, float w) {
    float th; asm("tanh.approx.f32 %0, %1;" : "=f"(th) : "f"(t));
    return th + a * __sinf(w * t);
}
__device__ __forceinline__ void cp_async16(uint32_t smem_dst, const void* gmem_src) {
    asm volatile("cp.async.cg.shared.global [%0], [%1], 16;" :: "r"(smem_dst), "l"(gmem_src));
}
__device__ __forceinline__ void ldsm4(uint32_t* r, uint32_t a) {
    asm volatile("ldmatrix.sync.aligned.m8n8.x4.shared.b16 {%0,%1,%2,%3}, [%4];"
                 : "=r"(r[0]), "=r"(r[1]), "=r"(r[2]), "=r"(r[3]) : "r"(a));
}
__device__ __forceinline__ void mma16816(float* d, const uint32_t* a,
                                         uint32_t b0, uint32_t b1) {
    asm volatile(
        "mma.sync.aligned.m16n8k16.row.col.f32.f16.f16.f32 "
        "{%0,%1,%2,%3}, {%4,%5,%6,%7}, {%8,%9}, {%0,%1,%2,%3};"
        : "+f"(d[0]), "+f"(d[1]), "+f"(d[2]), "+f"(d[3])
        : "r"(a[0]), "r"(a[1]), "r"(a[2]), "r"(a[3]), "r"(b0), "r"(b1));
}
// pack (x0,x1) to fp16x2 and store to X plane
__device__ __forceinline__ void store_x(uint32_t su, int p, int j,
                                        float x0, float x1) {
    uint32_t hx;
    asm("cvt.rn.f16x2.f32 %0, %1, %2;" : "=r"(hx) : "f"(x1), "f"(x0));
    uint32_t off = (uint32_t)(p * 256) + (uint32_t)((j * 2) ^ ((p & 7) << 4));
    asm volatile("st.shared.b32 [%0], %1;" :: "r"(su + SM_X + off), "r"(hx));
}
// stage one FULL layer of fp16 weights (32KB) into wbase and commit
__device__ __forceinline__ void stage_W(uint32_t wbase, const __half* src, int tid) {
#pragma unroll
    for (int i = 0; i < 8; i++)
        cp_async16(wbase + (uint32_t)(tid + i * 256) * 16,
                   (const char*)src + (tid + i * 256) * 16);
    asm volatile("cp.async.commit_group;");
}

// ---------------------------------------------------------------------------
// Branch MLP + gates + folded matrices (blocks 0..15) and weight prep
// (blocks 16..111): W^T + fp16 + SMEM-image swizzle into g_WT.
// ---------------------------------------------------------------------------
__global__ void __launch_bounds__(512, 1) branch_prep_kernel(
    const float* __restrict__ params, const float* __restrict__ Wb0,
    const float* __restrict__ bb0,    const float* __restrict__ Wb,
    const float* __restrict__ bb,     const float* __restrict__ Wbf,
    const float* __restrict__ bbf,    const float* __restrict__ ab,
    const float* __restrict__ wb,     const float* __restrict__ Wtf,
    const float* __restrict__ btf,    const float* __restrict__ Wt)
{
    const int tid = threadIdx.x;

    if (blockIdx.x >= NB) {
        // 96 blocks x 512 = 49152 = 3*16384 elements
        int idx = (blockIdx.x - NB) * 512 + tid;
        int k = idx & 127;
        int n = (idx >> 7) & 127;
        int l = idx >> 14;
        g_WT[l * 16384 + n * 128 + (k ^ ((n & 7) << 3))] =
            __float2half_rn(Wt[l * 16384 + k * 128 + n]);
        return;
    }

    const int b = blockIdx.x;
    const int j = tid & 127;
    const int q = tid >> 7;

    __shared__ float sh_h[HID];
    __shared__ float sh_part[4 * HID];
    __shared__ float sh_bc[OUTD][HID];
    __shared__ float sh_p[8];

    if (tid < 6) sh_p[tid] = params[b * 6 + tid];
    __syncthreads();

    float h = 0.f, gate = 0.f;
    if (q == 0) {
        float t = bb0[j];
#pragma unroll
        for (int k = 0; k < 6; k++) t += sh_p[k] * Wb0[k * HID + j];
        h = tanhf(t) + ab[j] * __sinf(wb[j] * t);
        gate = h;
        sh_h[j] = h;
        g_gate[(0 * NB + b) * HID + j] = gate;
    }
    __syncthreads();

    for (int i = 0; i < 3; i++) {
        const float* W = Wb + i * HID * HID;
        float tp = 0.f;
#pragma unroll 8
        for (int k = q * 32; k < q * 32 + 32; k++) tp += sh_h[k] * W[k * HID + j];
        sh_part[q * HID + j] = tp;
        __syncthreads();
        if (q == 0) {
            float t2 = bb[i * HID + j] + sh_part[j] + sh_part[HID + j]
                     + sh_part[2 * HID + j] + sh_part[3 * HID + j];
            h = tanhf(t2) + ab[(i + 1) * HID + j] * __sinf(wb[(i + 1) * HID + j] * t2);
            sh_h[j] = h;
            gate += h;
            g_gate[((i + 1) * NB + b) * HID + j] = gate;
        }
        __syncthreads();
    }

    {
        float tb[OUTD] = {0.f, 0.f, 0.f, 0.f, 0.f};
#pragma unroll 4
        for (int k = q * 32; k < q * 32 + 32; k++) {
            float hv = sh_h[k];
#pragma unroll
            for (int o = 0; o < OUTD; o++)
                tb[o] += hv * Wbf[k * (HID * OUTD) + o * HID + j];
        }
#pragma unroll
        for (int o = 0; o < OUTD; o++) {
            sh_part[q * HID + j] = tb[o];
            __syncthreads();
            if (q == 0)
                sh_bc[o][j] = bbf[o * HID + j] + sh_part[j] + sh_part[HID + j]
                            + sh_part[2 * HID + j] + sh_part[3 * HID + j];
            __syncthreads();
        }
    }

    {
        float am[OUTD] = {0.f, 0.f, 0.f, 0.f, 0.f};
#pragma unroll 4
        for (int hh = q * 32; hh < q * 32 + 32; hh++) {
            float w = __ldg(&Wtf[j * HID + hh]);
#pragma unroll
            for (int o = 0; o < OUTD; o++) am[o] += w * sh_bc[o][hh];
        }
#pragma unroll
        for (int o = 0; o < OUTD; o++) {
            sh_part[q * HID + j] = am[o];
            __syncthreads();
            if (q == 0)
                g_M[(b * HID + j) * 8 + o] = gate *
                    (sh_part[j] + sh_part[HID + j] + sh_part[2 * HID + j] + sh_part[3 * HID + j]);
            __syncthreads();
        }
        if (q == 0) { g_M[(b * HID + j) * 8 + 5] = 0.f;
                      g_M[(b * HID + j) * 8 + 6] = 0.f;
                      g_M[(b * HID + j) * 8 + 7] = 0.f; }
    }
    if (tid < OUTD) {
        float c = 0.f;
#pragma unroll 8
        for (int hh = 0; hh < HID; hh++) c += btf[hh] * sh_bc[tid][hh];
        g_c[b * 8 + tid] = c;
    }
    if (tid >= OUTD && tid < 8) g_c[b * 8 + tid] = 0.f;
}

// ---------------------------------------------------------------------------
// Trunk: HMMA fp16 single-plane W, full-layer double-buffered weights.
// 2 syncs/layer, 8 uninterrupted k-steps. 256 threads, 2M x 4N warp grid.
// ---------------------------------------------------------------------------
__global__ void __launch_bounds__(256, 2)
trunk_kernel(const float* __restrict__ coords, const float* __restrict__ sdf,
             const float* __restrict__ Wt0,    const float* __restrict__ bt0,
             const float* __restrict__ bt,     const float* __restrict__ at,
             const float* __restrict__ wt,     float* __restrict__ out)
{
    extern __shared__ char smem[];
    float* sp   = (float*)(smem + SM_PAR);
    float* scr  = (float*)(smem + SM_WA);       // L3 fp32 scratch: WA+WB (64KB)
    float* part = (float*)smem;                  // final partials alias X
    const uint32_t su = (uint32_t)__cvta_generic_to_shared(smem);

    const int tid  = threadIdx.x;
    const int lane = tid & 31;
    const int wid  = tid >> 5;
    const int wm   = wid & 1;                    // M half (64 rows)
    const int wn   = wid >> 1;                   // N quarter (32 cols)
    const int la7  = lane & 7;
    const int lb3  = (lane >> 3) & 1;
    const int lb4  = lane >> 4;
    const int gid  = lane >> 2;
    const int tig  = lane & 3;
    const uint32_t swz = (uint32_t)la7 << 4;

    const int p0     = blockIdx.x * BP;
    const int bstart = p0 / NPTS;
    const int bound  = (bstart + 1) * NPTS - p0;
    const int b1     = (bstart + 1 < NB) ? bstart + 1 : NB - 1;

    // G1: layer-1 W into WA (in flight during layer 0)
    stage_W(su + SM_WA, g_WT, tid);

    if (tid < 128) sp[PAR_BT0 + tid] = bt0[tid];
    for (int i = tid; i < 512; i += 256) {
        sp[PAR_W0 + i] = Wt0[i];
        sp[PAR_AT + i] = at[i];
        sp[PAR_WT + i] = wt[i];
    }
    for (int i = tid; i < 384; i += 256) sp[PAR_BT + i] = bt[i];
    __syncthreads();

    // ---- layer 0: 2 threads per point, 64 features each; writes X ----
    {
        const int p  = tid & 127;
        const int jh = tid >> 7;
        const int gp = p0 + p;
        float c0 = coords[gp * 3 + 0];
        float c1 = coords[gp * 3 + 1];
        float c2 = coords[gp * 3 + 2];
        float c3 = sdf[gp];
        const int bpt = (p < bound) ? bstart : b1;
        const float* gv = &g_gate[(0 * NB + bpt) * HID];
#pragma unroll 4
        for (int i = 0; i < 32; i++) {
            int j = jh * 64 + 2 * i;
            float t0 = sp[PAR_BT0 + j]
                     + c0 * sp[PAR_W0 + j]       + c1 * sp[PAR_W0 + 128 + j]
                     + c2 * sp[PAR_W0 + 256 + j] + c3 * sp[PAR_W0 + 384 + j];
            float t1 = sp[PAR_BT0 + j + 1]
                     + c0 * sp[PAR_W0 + j + 1]       + c1 * sp[PAR_W0 + 128 + j + 1]
                     + c2 * sp[PAR_W0 + 256 + j + 1] + c3 * sp[PAR_W0 + 384 + j + 1];
            float x0 = rowdy_f(t0, sp[PAR_AT + j], sp[PAR_WT + j]) * __ldg(&gv[j]);
            float x1 = rowdy_f(t1, sp[PAR_AT + j + 1], sp[PAR_WT + j + 1]) * __ldg(&gv[j + 1]);
            store_x(su, p, j, x0, x1);
        }
    }

    float acc[4][4][4];                          // [s: M 16-tile][t=q*2+u][4]

    // ---- layers 1..3 (W buffers: l1=WA, l2=WB, l3=WA) ----
    for (int l = 1; l <= 3; l++) {
        if (l == 1) stage_W(su + SM_WB, g_WT + 16384, tid);    // G2: l2 W
        // l1: pending {G1,G2} -> wait 1; l2: pending {G2,G3} -> wait 1;
        // l3: pending {G3} -> wait 0
        if (l < 3) asm volatile("cp.async.wait_group 1;");
        else       asm volatile("cp.async.wait_group 0;");
        __syncthreads();       // W ready + X writes visible

        const uint32_t wbase = su + ((l == 2) ? SM_WB : SM_WA);

#pragma unroll
        for (int s = 0; s < 4; s++)
#pragma unroll
            for (int t = 0; t < 4; t++)
#pragma unroll
                for (int i = 0; i < 4; i++) acc[s][t][i] = 0.f;

#pragma unroll
        for (int ks = 0; ks < 8; ks++) {
            uint32_t a[4][4];
#pragma unroll
            for (int s = 0; s < 4; s++) {
                uint32_t arow = (uint32_t)(wm * 64 + s * 16 + la7 + 8 * lb3);
                uint32_t aoff = ((uint32_t)(ks * 32 + 16 * lb4)) ^ swz;
                ldsm4(a[s], su + SM_X + arow * 256 + aoff);
            }
            uint32_t bh[2][4];
#pragma unroll
            for (int q = 0; q < 2; q++) {
                uint32_t nrow = (uint32_t)(wn * 32 + q * 16 + la7 + 8 * lb4);
                uint32_t boff = ((uint32_t)(ks * 32 + 16 * lb3)) ^ swz;
                ldsm4(bh[q], wbase + nrow * 256 + boff);
            }
#pragma unroll
            for (int s = 0; s < 4; s++)
#pragma unroll
                for (int q = 0; q < 2; q++)
#pragma unroll
                    for (int u = 0; u < 2; u++)
                        mma16816(acc[s][q * 2 + u], a[s], bh[q][2 * u], bh[q][2 * u + 1]);
        }
        __syncthreads();       // all X + W reads done

        if (l == 1) stage_W(su + SM_WA, g_WT + 2 * 16384, tid);  // G3: l3 W

        const float* bvec = &sp[PAR_BT + (l - 1) * 128];
        const float* avec = &sp[PAR_AT + l * 128];
        const float* wvec = &sp[PAR_WT + l * 128];
#pragma unroll
        for (int s = 0; s < 4; s++) {
            const int pA = wm * 64 + s * 16 + gid;
            const int bA = (pA < bound) ? bstart : b1;
            const int bB = (pA + 8 < bound) ? bstart : b1;
#pragma unroll
            for (int t = 0; t < 4; t++) {
                const int jA = wn * 32 + t * 8 + 2 * tig;
                float* d = acc[s][t];
                float x0 = rowdy_f(d[0] + bvec[jA],     avec[jA],     wvec[jA]);
                float x1 = rowdy_f(d[1] + bvec[jA + 1], avec[jA + 1], wvec[jA + 1]);
                float x2 = rowdy_f(d[2] + bvec[jA],     avec[jA],     wvec[jA]);
                float x3 = rowdy_f(d[3] + bvec[jA + 1], avec[jA + 1], wvec[jA + 1]);
                if (l < 3) {
                    const float* gA = &g_gate[(l * NB + bA) * HID];
                    const float* gB = &g_gate[(l * NB + bB) * HID];
                    x0 *= __ldg(&gA[jA]); x1 *= __ldg(&gA[jA + 1]);
                    x2 *= __ldg(&gB[jA]); x3 *= __ldg(&gB[jA + 1]);
                    store_x(su, pA,     jA, x0, x1);
                    store_x(su, pA + 8, jA, x2, x3);
                } else {
                    scr[jA * 128 + pA]           = x0;
                    scr[(jA + 1) * 128 + pA]     = x1;
                    scr[jA * 128 + pA + 8]       = x2;
                    scr[(jA + 1) * 128 + pA + 8] = x3;
                }
            }
        }
        if (l == 3) __syncthreads();   // scr complete before contraction
        // l<3: next layer's top sync orders X writes
    }

    // ---- folded final: out[p][o] = c[b][o] + sum_g x[p][g] * M'[b][g][o] ----
    {
        const int p = tid & 127;
        const int q = tid >> 7;
        const int b = (p < bound) ? bstart : b1;
        float o0 = 0.f, o1 = 0.f, o2 = 0.f, o3 = 0.f, o4 = 0.f;
        const float4* Mb = (const float4*)&g_M[b * HID * 8];
#pragma unroll 8
        for (int g = q * 64; g < q * 64 + 64; g++) {
            float v   = scr[g * 128 + p];
            float4 m0 = __ldg(&Mb[g * 2 + 0]);
            float4 m1 = __ldg(&Mb[g * 2 + 1]);
            o0 += v * m0.x; o1 += v * m0.y; o2 += v * m0.z; o3 += v * m0.w;
            o4 += v * m1.x;
        }
        part[(0 * 2 + q) * 128 + p] = o0;
        part[(1 * 2 + q) * 128 + p] = o1;
        part[(2 * 2 + q) * 128 + p] = o2;
        part[(3 * 2 + q) * 128 + p] = o3;
        part[(4 * 2 + q) * 128 + p] = o4;
        __syncthreads();
        if (tid < BP) {
            const int gp = p0 + tid;
            const int b2 = (tid < bound) ? bstart : b1;
            float* op = out + (size_t)gp * OUTD;
#pragma unroll
            for (int o = 0; o < OUTD; o++)
                op[o] = g_c[b2 * 8 + o]
                      + part[(o * 2 + 0) * 128 + tid]
                      + part[(o * 2 + 1) * 128 + tid];
        }
    }
}

// ---------------------------------------------------------------------------
extern "C" void kernel_launch(void* const* d_in, const int* in_sizes, int n_in,
                              void* d_out, int out_size)
{
    const float* coords = (const float*)d_in[0];
    const float* sdf    = (const float*)d_in[1];
    const float* params = (const float*)d_in[2];
    const float* Wb0    = (const float*)d_in[3];
    const float* bb0    = (const float*)d_in[4];
    const float* Wb     = (const float*)d_in[5];
    const float* bb     = (const float*)d_in[6];
    const float* Wbf    = (const float*)d_in[7];
    const float* bbf    = (const float*)d_in[8];
    const float* ab     = (const float*)d_in[9];
    const float* wb     = (const float*)d_in[10];
    const float* Wt0    = (const float*)d_in[11];
    const float* bt0    = (const float*)d_in[12];
    const float* Wt     = (const float*)d_in[13];
    const float* bt     = (const float*)d_in[14];
    const float* Wtf    = (const float*)d_in[15];
    const float* btf    = (const float*)d_in[16];
    const float* at     = (const float*)d_in[17];
    const float* wt     = (const float*)d_in[18];
    float* out = (float*)d_out;

    static int smem_set = 0;
    if (!smem_set) {
        cudaFuncSetAttribute(trunk_kernel,
                             cudaFuncAttributeMaxDynamicSharedMemorySize,
                             SM_TOTAL);
        smem_set = 1;
    }

    branch_prep_kernel<<<NB + 96, 512>>>(params, Wb0, bb0, Wb, bb, Wbf, bbf,
                                         ab, wb, Wtf, btf, Wt);
    trunk_kernel<<<LTOT / BP, 256, SM_TOTAL>>>(coords, sdf, Wt0, bt0,
                                               bt, at, wt, out);
}

// round 14
// speedup vs baseline: 1.4372x; 1.0533x over previous
#include <cuda_runtime.h>
#include <cuda_fp16.h>
#include <cstdint>

#define HID   128
#define NB    16
#define NPTS  10000
#define OUTD  5
#define BP    128
#define BPB   79                 // blocks per batch (79*128 = 10112 >= 10000)

// ---------------- device scratch (no allocation allowed) -------------------
__device__ float g_gate[4 * NB * HID];
__device__ float g_M[NB * HID * 8];      // gate3-folded Wtf@bc^T, padded 8
__device__ float g_c[NB * 8];
// Per-batch gate-folded, transposed, swizzled fp16 weights:
// [l:3][b:16][n=128][k=128]  (32KB per (l,b))
__device__ __align__(16) __half g_WTb[3 * NB * 16384];

// SMEM byte map (per CTA, dynamic):
//  [0,32768)       X plane [128 p][128 k] fp16, row 256B, swz ((p&7)<<4)
//  [32768,65536)   WA: FULL-layer weights [128 n][128 k] fp16
//  [65536,98304)   WB: double buffer
//  [98304,106496)  params (2048 floats)
//  L3 fp32 scratch aliases WA+WB; partials alias X.
#define SM_X   0
#define SM_WA  32768
#define SM_WB  65536
#define SM_PAR 98304
#define SM_TOTAL 106496
#define PAR_BT0 0
#define PAR_W0  128
#define PAR_AT  640
#define PAR_WT  1152
#define PAR_BT  1664

__device__ __forceinline__ float rowdy_f(float t, float a, float w) {
    float th; asm("tanh.approx.f32 %0, %1;" : "=f"(th) : "f"(t));
    return th + a * __sinf(w * t);
}
__device__ __forceinline__ void cp_async16(uint32_t smem_dst, const void* gmem_src) {
    asm volatile("cp.async.cg.shared.global [%0], [%1], 16;" :: "r"(smem_dst), "l"(gmem_src));
}
__device__ __forceinline__ void ldsm4(uint32_t* r, uint32_t a) {
    asm volatile("ldmatrix.sync.aligned.m8n8.x4.shared.b16 {%0,%1,%2,%3}, [%4];"
                 : "=r"(r[0]), "=r"(r[1]), "=r"(r[2]), "=r"(r[3]) : "r"(a));
}
__device__ __forceinline__ void mma16816(float* d, const uint32_t* a,
                                         uint32_t b0, uint32_t b1) {
    asm volatile(
        "mma.sync.aligned.m16n8k16.row.col.f32.f16.f16.f32 "
        "{%0,%1,%2,%3}, {%4,%5,%6,%7}, {%8,%9}, {%0,%1,%2,%3};"
        : "+f"(d[0]), "+f"(d[1]), "+f"(d[2]), "+f"(d[3])
        : "r"(a[0]), "r"(a[1]), "r"(a[2]), "r"(a[3]), "r"(b0), "r"(b1));
}
__device__ __forceinline__ void store_x(uint32_t su, int p, int j,
                                        float x0, float x1) {
    uint32_t hx;
    asm("cvt.rn.f16x2.f32 %0, %1, %2;" : "=r"(hx) : "f"(x1), "f"(x0));
    uint32_t off = (uint32_t)(p * 256) + (uint32_t)((j * 2) ^ ((p & 7) << 4));
    asm volatile("st.shared.b32 [%0], %1;" :: "r"(su + SM_X + off), "r"(hx));
}
__device__ __forceinline__ void stage_W(uint32_t wbase, const __half* src, int tid) {
#pragma unroll
    for (int i = 0; i < 8; i++)
        cp_async16(wbase + (uint32_t)(tid + i * 256) * 16,
                   (const char*)src + (tid + i * 256) * 16);
    asm volatile("cp.async.commit_group;");
}

// ---------------------------------------------------------------------------
// Kernel 1: branch MLP + gates + folded matrices. grid=16, block=512.
// ---------------------------------------------------------------------------
__global__ void __launch_bounds__(512, 1) branch_kernel(
    const float* __restrict__ params, const float* __restrict__ Wb0,
    const float* __restrict__ bb0,    const float* __restrict__ Wb,
    const float* __restrict__ bb,     const float* __restrict__ Wbf,
    const float* __restrict__ bbf,    const float* __restrict__ ab,
    const float* __restrict__ wb,     const float* __restrict__ Wtf,
    const float* __restrict__ btf)
{
    const int b   = blockIdx.x;
    const int tid = threadIdx.x;
    const int j   = tid & 127;
    const int q   = tid >> 7;

    __shared__ float sh_h[HID];
    __shared__ float sh_part[4 * HID];
    __shared__ float sh_bc[OUTD][HID];
    __shared__ float sh_p[8];

    if (tid < 6) sh_p[tid] = params[b * 6 + tid];
    __syncthreads();

    float h = 0.f, gate = 0.f;
    if (q == 0) {
        float t = bb0[j];
#pragma unroll
        for (int k = 0; k < 6; k++) t += sh_p[k] * Wb0[k * HID + j];
        h = tanhf(t) + ab[j] * __sinf(wb[j] * t);
        gate = h;
        sh_h[j] = h;
        g_gate[(0 * NB + b) * HID + j] = gate;
    }
    __syncthreads();

    for (int i = 0; i < 3; i++) {
        const float* W = Wb + i * HID * HID;
        float tp = 0.f;
#pragma unroll 8
        for (int k = q * 32; k < q * 32 + 32; k++) tp += sh_h[k] * W[k * HID + j];
        sh_part[q * HID + j] = tp;
        __syncthreads();
        if (q == 0) {
            float t2 = bb[i * HID + j] + sh_part[j] + sh_part[HID + j]
                     + sh_part[2 * HID + j] + sh_part[3 * HID + j];
            h = tanhf(t2) + ab[(i + 1) * HID + j] * __sinf(wb[(i + 1) * HID + j] * t2);
            sh_h[j] = h;
            gate += h;
            g_gate[((i + 1) * NB + b) * HID + j] = gate;
        }
        __syncthreads();
    }

    {
        float tb[OUTD] = {0.f, 0.f, 0.f, 0.f, 0.f};
#pragma unroll 4
        for (int k = q * 32; k < q * 32 + 32; k++) {
            float hv = sh_h[k];
#pragma unroll
            for (int o = 0; o < OUTD; o++)
                tb[o] += hv * Wbf[k * (HID * OUTD) + o * HID + j];
        }
#pragma unroll
        for (int o = 0; o < OUTD; o++) {
            sh_part[q * HID + j] = tb[o];
            __syncthreads();
            if (q == 0)
                sh_bc[o][j] = bbf[o * HID + j] + sh_part[j] + sh_part[HID + j]
                            + sh_part[2 * HID + j] + sh_part[3 * HID + j];
            __syncthreads();
        }
    }

    {
        float am[OUTD] = {0.f, 0.f, 0.f, 0.f, 0.f};
#pragma unroll 4
        for (int hh = q * 32; hh < q * 32 + 32; hh++) {
            float w = __ldg(&Wtf[j * HID + hh]);
#pragma unroll
            for (int o = 0; o < OUTD; o++) am[o] += w * sh_bc[o][hh];
        }
#pragma unroll
        for (int o = 0; o < OUTD; o++) {
            sh_part[q * HID + j] = am[o];
            __syncthreads();
            if (q == 0)
                g_M[(b * HID + j) * 8 + o] = gate *
                    (sh_part[j] + sh_part[HID + j] + sh_part[2 * HID + j] + sh_part[3 * HID + j]);
            __syncthreads();
        }
        if (q == 0) { g_M[(b * HID + j) * 8 + 5] = 0.f;
                      g_M[(b * HID + j) * 8 + 6] = 0.f;
                      g_M[(b * HID + j) * 8 + 7] = 0.f; }
    }
    if (tid < OUTD) {
        float c = 0.f;
#pragma unroll 8
        for (int hh = 0; hh < HID; hh++) c += btf[hh] * sh_bc[tid][hh];
        g_c[b * 8 + tid] = c;
    }
    if (tid >= OUTD && tid < 8) g_c[b * 8 + tid] = 0.f;
}

// ---------------------------------------------------------------------------
// Kernel 2: weight prep — gate-folded per-batch W^T, fp16, swizzled.
// 786432 elems; runs after branch (reads g_gate).
// ---------------------------------------------------------------------------
__global__ void __launch_bounds__(512, 2) prep_kernel(const float* __restrict__ Wt) {
    int idx = blockIdx.x * 512 + threadIdx.x;     // < 3*16*16384
    int k = idx & 127;
    int n = (idx >> 7) & 127;
    int b = (idx >> 14) & 15;
    int l = idx >> 18;                            // 0..2 (trunk layer l+1)
    float w = Wt[l * 16384 + k * 128 + n] * g_gate[(l * NB + b) * HID + k];
    g_WTb[(l * NB + b) * 16384 + n * 128 + (k ^ ((n & 7) << 3))] =
        __float2half_rn(w);
}

// ---------------------------------------------------------------------------
// Kernel 3: trunk. Batch-aligned blocks (79/batch), gate-free epilogues,
// full-layer double-buffered W. 256 threads, 2M x 4N warp grid.
// ---------------------------------------------------------------------------
__global__ void __launch_bounds__(256, 2)
trunk_kernel(const float* __restrict__ coords, const float* __restrict__ sdf,
             const float* __restrict__ Wt0,    const float* __restrict__ bt0,
             const float* __restrict__ bt,     const float* __restrict__ at,
             const float* __restrict__ wt,     float* __restrict__ out)
{
    extern __shared__ char smem[];
    float* sp   = (float*)(smem + SM_PAR);
    float* scr  = (float*)(smem + SM_WA);       // L3 fp32 scratch: WA+WB
    float* part = (float*)smem;                  // final partials alias X
    const uint32_t su = (uint32_t)__cvta_generic_to_shared(smem);

    const int tid  = threadIdx.x;
    const int lane = tid & 31;
    const int wid  = tid >> 5;
    const int wm   = wid & 1;
    const int wn   = wid >> 1;
    const int la7  = lane & 7;
    const int lb3  = (lane >> 3) & 1;
    const int lb4  = lane >> 4;
    const int gid  = lane >> 2;
    const int tig  = lane & 3;
    const uint32_t swz = (uint32_t)la7 << 4;

    const int bat   = blockIdx.x / BPB;          // batch
    const int pbase = (blockIdx.x - bat * BPB) * BP;
    const int valid = (NPTS - pbase < BP) ? (NPTS - pbase) : BP;
    const int gp0   = bat * NPTS + pbase;
    const __half* Wsrc = g_WTb + (size_t)bat * 16384;   // + l*NB*16384

    // G1: layer-1 W into WA
    stage_W(su + SM_WA, Wsrc + 0 * NB * 16384, tid);

    if (tid < 128) sp[PAR_BT0 + tid] = bt0[tid];
    for (int i = tid; i < 512; i += 256) {
        sp[PAR_W0 + i] = Wt0[i];
        sp[PAR_AT + i] = at[i];
        sp[PAR_WT + i] = wt[i];
    }
    for (int i = tid; i < 384; i += 256) sp[PAR_BT + i] = bt[i];
    __syncthreads();

    // ---- layer 0: 2 threads per point; gate0 folded into W1' ----
    {
        const int p  = tid & 127;
        const int jh = tid >> 7;
        float c0 = 0.f, c1 = 0.f, c2 = 0.f, c3 = 0.f;
        if (p < valid) {
            int gp = gp0 + p;
            c0 = coords[gp * 3 + 0];
            c1 = coords[gp * 3 + 1];
            c2 = coords[gp * 3 + 2];
            c3 = sdf[gp];
        }
#pragma unroll 4
        for (int i = 0; i < 32; i++) {
            int j = jh * 64 + 2 * i;
            float t0 = sp[PAR_BT0 + j]
                     + c0 * sp[PAR_W0 + j]       + c1 * sp[PAR_W0 + 128 + j]
                     + c2 * sp[PAR_W0 + 256 + j] + c3 * sp[PAR_W0 + 384 + j];
            float t1 = sp[PAR_BT0 + j + 1]
                     + c0 * sp[PAR_W0 + j + 1]       + c1 * sp[PAR_W0 + 128 + j + 1]
                     + c2 * sp[PAR_W0 + 256 + j + 1] + c3 * sp[PAR_W0 + 384 + j + 1];
            float x0 = rowdy_f(t0, sp[PAR_AT + j],     sp[PAR_WT + j]);
            float x1 = rowdy_f(t1, sp[PAR_AT + j + 1], sp[PAR_WT + j + 1]);
            store_x(su, p, j, x0, x1);
        }
    }

    float acc[4][4][4];

    // ---- layers 1..3 (W buffers: l1=WA, l2=WB, l3=WA) ----
    for (int l = 1; l <= 3; l++) {
        if (l == 1) stage_W(su + SM_WB, Wsrc + 1 * NB * 16384, tid);   // G2
        if (l < 3) asm volatile("cp.async.wait_group 1;");
        else       asm volatile("cp.async.wait_group 0;");
        __syncthreads();

        const uint32_t wbase = su + ((l == 2) ? SM_WB : SM_WA);

#pragma unroll
        for (int s = 0; s < 4; s++)
#pragma unroll
            for (int t = 0; t < 4; t++)
#pragma unroll
                for (int i = 0; i < 4; i++) acc[s][t][i] = 0.f;

#pragma unroll
        for (int ks = 0; ks < 8; ks++) {
            uint32_t a[4][4];
#pragma unroll
            for (int s = 0; s < 4; s++) {
                uint32_t arow = (uint32_t)(wm * 64 + s * 16 + la7 + 8 * lb3);
                uint32_t aoff = ((uint32_t)(ks * 32 + 16 * lb4)) ^ swz;
                ldsm4(a[s], su + SM_X + arow * 256 + aoff);
            }
            uint32_t bh[2][4];
#pragma unroll
            for (int q = 0; q < 2; q++) {
                uint32_t nrow = (uint32_t)(wn * 32 + q * 16 + la7 + 8 * lb4);
                uint32_t boff = ((uint32_t)(ks * 32 + 16 * lb3)) ^ swz;
                ldsm4(bh[q], wbase + nrow * 256 + boff);
            }
#pragma unroll
            for (int s = 0; s < 4; s++)
#pragma unroll
                for (int q = 0; q < 2; q++)
#pragma unroll
                    for (int u = 0; u < 2; u++)
                        mma16816(acc[s][q * 2 + u], a[s], bh[q][2 * u], bh[q][2 * u + 1]);
        }
        __syncthreads();

        if (l == 1) stage_W(su + SM_WA, Wsrc + 2 * NB * 16384, tid);   // G3

        const float* bvec = &sp[PAR_BT + (l - 1) * 128];
        const float* avec = &sp[PAR_AT + l * 128];
        const float* wvec = &sp[PAR_WT + l * 128];
#pragma unroll
        for (int s = 0; s < 4; s++) {
            const int pA = wm * 64 + s * 16 + gid;
#pragma unroll
            for (int t = 0; t < 4; t++) {
                const int jA = wn * 32 + t * 8 + 2 * tig;
                float* d = acc[s][t];
                float x0 = rowdy_f(d[0] + bvec[jA],     avec[jA],     wvec[jA]);
                float x1 = rowdy_f(d[1] + bvec[jA + 1], avec[jA + 1], wvec[jA + 1]);
                float x2 = rowdy_f(d[2] + bvec[jA],     avec[jA],     wvec[jA]);
                float x3 = rowdy_f(d[3] + bvec[jA + 1], avec[jA + 1], wvec[jA + 1]);
                if (l < 3) {
                    store_x(su, pA,     jA, x0, x1);
                    store_x(su, pA + 8, jA, x2, x3);
                } else {
                    scr[jA * 128 + pA]           = x0;
                    scr[(jA + 1) * 128 + pA]     = x1;
                    scr[jA * 128 + pA + 8]       = x2;
                    scr[(jA + 1) * 128 + pA + 8] = x3;
                }
            }
        }
        if (l == 3) __syncthreads();
    }

    // ---- folded final: out[p][o] = c[b][o] + sum_g x[p][g] * M'[b][g][o] ----
    {
        const int p = tid & 127;
        const int q = tid >> 7;
        float o0 = 0.f, o1 = 0.f, o2 = 0.f, o3 = 0.f, o4 = 0.f;
        const float4* Mb = (const float4*)&g_M[bat * HID * 8];
#pragma unroll 8
        for (int g = q * 64; g < q * 64 + 64; g++) {
            float v   = scr[g * 128 + p];
            float4 m0 = __ldg(&Mb[g * 2 + 0]);
            float4 m1 = __ldg(&Mb[g * 2 + 1]);
            o0 += v * m0.x; o1 += v * m0.y; o2 += v * m0.z; o3 += v * m0.w;
            o4 += v * m1.x;
        }
        part[(0 * 2 + q) * 128 + p] = o0;
        part[(1 * 2 + q) * 128 + p] = o1;
        part[(2 * 2 + q) * 128 + p] = o2;
        part[(3 * 2 + q) * 128 + p] = o3;
        part[(4 * 2 + q) * 128 + p] = o4;
        __syncthreads();
        if (tid < valid) {
            const int gp = gp0 + tid;
            float* op = out + (size_t)gp * OUTD;
#pragma unroll
            for (int o = 0; o < OUTD; o++)
                op[o] = g_c[bat * 8 + o]
                      + part[(o * 2 + 0) * 128 + tid]
                      + part[(o * 2 + 1) * 128 + tid];
        }
    }
}

// ---------------------------------------------------------------------------
extern "C" void kernel_launch(void* const* d_in, const int* in_sizes, int n_in,
                              void* d_out, int out_size)
{
    const float* coords = (const float*)d_in[0];
    const float* sdf    = (const float*)d_in[1];
    const float* params = (const float*)d_in[2];
    const float* Wb0    = (const float*)d_in[3];
    const float* bb0    = (const float*)d_in[4];
    const float* Wb     = (const float*)d_in[5];
    const float* bb     = (const float*)d_in[6];
    const float* Wbf    = (const float*)d_in[7];
    const float* bbf    = (const float*)d_in[8];
    const float* ab     = (const float*)d_in[9];
    const float* wb     = (const float*)d_in[10];
    const float* Wt0    = (const float*)d_in[11];
    const float* bt0    = (const float*)d_in[12];
    const float* Wt     = (const float*)d_in[13];
    const float* bt     = (const float*)d_in[14];
    const float* Wtf    = (const float*)d_in[15];
    const float* btf    = (const float*)d_in[16];
    const float* at     = (const float*)d_in[17];
    const float* wt     = (const float*)d_in[18];
    float* out = (float*)d_out;

    static int smem_set = 0;
    if (!smem_set) {
        cudaFuncSetAttribute(trunk_kernel,
                             cudaFuncAttributeMaxDynamicSharedMemorySize,
                             SM_TOTAL);
        smem_set = 1;
    }

    branch_kernel<<<NB, 512>>>(params, Wb0, bb0, Wb, bb, Wbf, bbf, ab, wb,
                               Wtf, btf);
    prep_kernel<<<(3 * NB * 16384) / 512, 512>>>(Wt);
    trunk_kernel<<<NB * BPB, 256, SM_TOTAL>>>(coords, sdf, Wt0, bt0,
                                              bt, at, wt, out);
}